// round 1
// baseline (speedup 1.0000x reference)
#include <cuda_runtime.h>

#define NN 100000
#define NE 1600000
#define NG 64
#define DD 128
#define NBS 98            // ceil(100000/1024)
#define EPSX 1e-5f

// ---------------- scratch (static device globals; no allocation) ----------------
__device__ __align__(16) float g_bufA[NN * DD];   // message-ready features (pre-scaled by norm_src)
__device__ __align__(16) float g_bufB[NN * DD];   // agg / gemm output (in-place)
__device__ int   g_csr[NE];
__device__ int   g_off[NN];
__device__ int   g_cur[NN];
__device__ int   g_degin[NN];
__device__ int   g_degout[NN];
__device__ float g_nsrc[NN];
__device__ float g_ndst[NN];
__device__ int   g_part[NBS];
__device__ int   g_partoff[NBS];
__device__ __align__(16) float g_sum[DD];
__device__ __align__(16) float g_sq[DD];
__device__ __align__(16) float g_scale[DD];
__device__ __align__(16) float g_shift[DD];
__device__ int   g_gcnt[NG];
__device__ __align__(16) float g_hg[NG * DD];

// ---------------- fp32x2 packed-FMA helpers (Blackwell sm_100+) ----------------
__device__ __forceinline__ unsigned long long pk2(float a) {
    unsigned long long r;
    asm("mov.b64 %0, {%1, %1};" : "=l"(r) : "f"(a));
    return r;
}
__device__ __forceinline__ unsigned long long fma2(unsigned long long a,
                                                   unsigned long long b,
                                                   unsigned long long c) {
    unsigned long long d;
    asm("fma.rn.f32x2 %0, %1, %2, %3;" : "=l"(d) : "l"(a), "l"(b), "l"(c));
    return d;
}
__device__ __forceinline__ float2 upk2(unsigned long long v) {
    float2 f;
    asm("mov.b64 {%0, %1}, %2;" : "=f"(f.x), "=f"(f.y) : "l"(v));
    return f;
}

// ---------------- setup kernels ----------------
__global__ void k_zero() {
    int i = blockIdx.x * 256 + threadIdx.x;
    if (i < NN) { g_degin[i] = 0; g_degout[i] = 0; }
    if (i < NG) g_gcnt[i] = 0;
    if (i < NG * DD) g_hg[i] = 0.0f;
}

__global__ void k_deg(const int* __restrict__ src, const int* __restrict__ dst) {
    int e = blockIdx.x * 256 + threadIdx.x;
    if (e < NE) {
        atomicAdd(&g_degout[src[e]], 1);
        atomicAdd(&g_degin[dst[e]], 1);
    }
}

__global__ void k_gcnt(const int* __restrict__ gids) {
    int v = blockIdx.x * 256 + threadIdx.x;
    if (v < NN) atomicAdd(&g_gcnt[gids[v]], 1);
}

__global__ void k_norm() {
    int v = blockIdx.x * 256 + threadIdx.x;
    if (v < NN) {
        g_nsrc[v] = rsqrtf((float)max(g_degout[v], 1));
        g_ndst[v] = rsqrtf((float)max(g_degin[v], 1));
    }
}

__global__ void k_scan1() {
    int tid = threadIdx.x;
    int gid = blockIdx.x * 1024 + tid;
    int v = (gid < NN) ? g_degin[gid] : 0;
    int lane = tid & 31, w = tid >> 5;
    int x = v;
#pragma unroll
    for (int o = 1; o < 32; o <<= 1) {
        int y = __shfl_up_sync(0xffffffffu, x, o);
        if (lane >= o) x += y;
    }
    __shared__ int ws[32];
    if (lane == 31) ws[w] = x;
    __syncthreads();
    if (w == 0) {
        int y = ws[lane];
#pragma unroll
        for (int o = 1; o < 32; o <<= 1) {
            int z = __shfl_up_sync(0xffffffffu, y, o);
            if (lane >= o) y += z;
        }
        ws[lane] = y;
    }
    __syncthreads();
    int incl = x + (w ? ws[w - 1] : 0);
    if (gid < NN) g_off[gid] = incl - v;    // exclusive
    if (tid == 1023) g_part[blockIdx.x] = incl;
}

__global__ void k_scan2() {
    if (threadIdx.x == 0) {
        int acc = 0;
        for (int i = 0; i < NBS; i++) { int t = g_part[i]; g_partoff[i] = acc; acc += t; }
    }
}

__global__ void k_scan3() {
    int gid = blockIdx.x * 1024 + threadIdx.x;
    if (gid < NN) {
        int o = g_off[gid] + g_partoff[blockIdx.x];
        g_off[gid] = o;
        g_cur[gid] = o;
    }
}

__global__ void k_scatter(const int* __restrict__ src, const int* __restrict__ dst) {
    int e = blockIdx.x * 256 + threadIdx.x;
    if (e < NE) {
        int d = dst[e];
        int pos = atomicAdd(&g_cur[d], 1);
        g_csr[pos] = src[e];
    }
}

// h0 = embed[tokens] * norm_src  (message-ready)
__global__ void k_embed(const int* __restrict__ tokens, const float* __restrict__ embed) {
    int idx = blockIdx.x * 256 + threadIdx.x;
    if (idx >= NN * 32) return;
    int v = idx >> 5, q = idx & 31;
    int t = tokens[v];
    float4 e = ((const float4*)embed)[t * 32 + q];
    float ns = g_nsrc[v];
    e.x *= ns; e.y *= ns; e.z *= ns; e.w *= ns;
    ((float4*)g_bufA)[idx] = e;
}

// ---------------- per-layer kernels ----------------
// agg[v] = norm_dst[v] * sum_{e: dst=v} bufA[src[e]]   (one warp per node)
__global__ void k_agg() {
    int wid = (blockIdx.x * blockDim.x + threadIdx.x) >> 5;
    int lane = threadIdx.x & 31;
    if (wid >= NN) return;
    int off = g_off[wid];
    int deg = g_degin[wid];
    const float4* src4 = (const float4*)g_bufA;
    float4 a0 = make_float4(0, 0, 0, 0);
    float4 a1 = make_float4(0, 0, 0, 0);
    int i = 0;
    for (; i + 1 < deg; i += 2) {
        int s0 = g_csr[off + i];
        int s1 = g_csr[off + i + 1];
        float4 m0 = src4[s0 * 32 + lane];
        float4 m1 = src4[s1 * 32 + lane];
        a0.x += m0.x; a0.y += m0.y; a0.z += m0.z; a0.w += m0.w;
        a1.x += m1.x; a1.y += m1.y; a1.z += m1.z; a1.w += m1.w;
    }
    if (i < deg) {
        int s0 = g_csr[off + i];
        float4 m0 = src4[s0 * 32 + lane];
        a0.x += m0.x; a0.y += m0.y; a0.z += m0.z; a0.w += m0.w;
    }
    float nd = g_ndst[wid];
    float4 r;
    r.x = (a0.x + a1.x) * nd;
    r.y = (a0.y + a1.y) * nd;
    r.z = (a0.z + a1.z) * nd;
    r.w = (a0.w + a1.w) * nd;
    ((float4*)g_bufB)[wid * 32 + lane] = r;
}

// in-place  bufB = bufB @ W + b    (64 rows x 128 cols per block, fp32x2 FMA)
__global__ __launch_bounds__(128) void k_gemm(const float* __restrict__ W,
                                              const float* __restrict__ bias) {
    __shared__ float Wsm[32 * 128];   // one 32-row K chunk of W
    __shared__ float Xs[32 * 68];     // transposed X chunk [k][r], pad 68
    int tid = threadIdx.x;
    int tx = tid & 15, ty = tid >> 4;
    int rbase = blockIdx.x * 64;
    unsigned long long c2[8][4];
#pragma unroll
    for (int i = 0; i < 8; i++)
#pragma unroll
        for (int j = 0; j < 4; j++) c2[i][j] = 0ull;

    const float4* io4 = (const float4*)g_bufB;

    for (int kc = 0; kc < 4; kc++) {
        // stage W chunk: 1024 float4
        const float4* Wg = (const float4*)(W + kc * 32 * 128);
        float4* Ws4 = (float4*)Wsm;
#pragma unroll
        for (int i = 0; i < 8; i++) Ws4[tid + i * 128] = Wg[tid + i * 128];
        // stage X chunk transposed: 512 float4
#pragma unroll
        for (int i = 0; i < 4; i++) {
            int f = tid + i * 128;        // 0..511
            int r = f >> 3;               // 0..63
            int k4 = f & 7;               // float4 within 32-k chunk
            float4 v = make_float4(0, 0, 0, 0);
            int row = rbase + r;
            if (row < NN) v = io4[row * 32 + kc * 8 + k4];
            Xs[(k4 * 4 + 0) * 68 + r] = v.x;
            Xs[(k4 * 4 + 1) * 68 + r] = v.y;
            Xs[(k4 * 4 + 2) * 68 + r] = v.z;
            Xs[(k4 * 4 + 3) * 68 + r] = v.w;
        }
        __syncthreads();
#pragma unroll 8
        for (int k = 0; k < 32; k++) {
            float4 av0 = *(const float4*)&Xs[k * 68 + ty * 8];
            float4 av1 = *(const float4*)&Xs[k * 68 + ty * 8 + 4];
            const unsigned long long* wrow =
                (const unsigned long long*)&Wsm[k * 128 + tx * 8];
            unsigned long long b0 = wrow[0], b1 = wrow[1], b2 = wrow[2], b3 = wrow[3];
            float a[8] = {av0.x, av0.y, av0.z, av0.w, av1.x, av1.y, av1.z, av1.w};
#pragma unroll
            for (int i = 0; i < 8; i++) {
                unsigned long long ap = pk2(a[i]);
                c2[i][0] = fma2(ap, b0, c2[i][0]);
                c2[i][1] = fma2(ap, b1, c2[i][1]);
                c2[i][2] = fma2(ap, b2, c2[i][2]);
                c2[i][3] = fma2(ap, b3, c2[i][3]);
            }
        }
        __syncthreads();
    }
    // epilogue: bias + store
    float4 bi0 = *(const float4*)&bias[tx * 8];
    float4 bi1 = *(const float4*)&bias[tx * 8 + 4];
    float4* out4 = (float4*)g_bufB;
#pragma unroll
    for (int i = 0; i < 8; i++) {
        int row = rbase + ty * 8 + i;
        if (row >= NN) break;
        float2 p0 = upk2(c2[i][0]), p1 = upk2(c2[i][1]);
        float2 p2 = upk2(c2[i][2]), p3 = upk2(c2[i][3]);
        float4 o0 = make_float4(p0.x + bi0.x, p0.y + bi0.y, p1.x + bi0.z, p1.y + bi0.w);
        float4 o1 = make_float4(p2.x + bi1.x, p2.y + bi1.y, p3.x + bi1.z, p3.y + bi1.w);
        out4[row * 32 + tx * 2] = o0;
        out4[row * 32 + tx * 2 + 1] = o1;
    }
}

__global__ void k_zstat() {
    int c = threadIdx.x;
    g_sum[c] = 0.0f;
    g_sq[c] = 0.0f;
}

__global__ void k_stat() {
    int c = threadIdx.x;           // 128 threads
    float s = 0.0f, q = 0.0f;
    for (int r = blockIdx.x; r < NN; r += gridDim.x) {
        float v = g_bufB[r * DD + c];
        s += v;
        q += v * v;
    }
    atomicAdd(&g_sum[c], s);
    atomicAdd(&g_sq[c], q);
}

__global__ void k_bnfinal(const float* __restrict__ gamma, const float* __restrict__ beta) {
    int c = threadIdx.x;
    const float invn = 1.0f / (float)NN;
    float mu = g_sum[c] * invn;
    float var = g_sq[c] * invn - mu * mu;
    var = fmaxf(var, 0.0f);
    float sc = gamma[c] * rsqrtf(var + EPSX);
    g_scale[c] = sc;
    g_shift[c] = beta[c] - mu * sc;
}

// layers 0/1: bufA = relu(bn(bufB)) * norm_src   (message-ready for next layer)
__global__ void k_apply() {
    int idx = blockIdx.x * 256 + threadIdx.x;
    if (idx >= NN * 32) return;
    int v = idx >> 5, q = idx & 31;
    float4 y = ((const float4*)g_bufB)[idx];
    float4 sc = ((const float4*)g_scale)[q];
    float4 sh = ((const float4*)g_shift)[q];
    float ns = g_nsrc[v];
    float4 r;
    r.x = fmaxf(fmaf(y.x, sc.x, sh.x), 0.0f) * ns;
    r.y = fmaxf(fmaf(y.y, sc.y, sh.y), 0.0f) * ns;
    r.z = fmaxf(fmaf(y.z, sc.z, sh.z), 0.0f) * ns;
    r.w = fmaxf(fmaf(y.w, sc.w, sh.w), 0.0f) * ns;
    ((float4*)g_bufA)[idx] = r;
}

// layer 2: relu(bn(bufB)) pooled per graph (warp-reduced; graph_ids sorted)
__global__ void k_pool(const int* __restrict__ gids) {
    int w = threadIdx.x >> 5, lane = threadIdx.x & 31;
    int v = blockIdx.x * 32 + lane;
    bool valid = v < NN;
    int g = valid ? gids[v] : 0;
    int g0 = __shfl_sync(0xffffffffu, g, 0);
    bool uni = __all_sync(0xffffffffu, valid && g == g0);
#pragma unroll
    for (int qq = 0; qq < 4; qq++) {
        int q = w * 4 + qq;            // 0..31
        float4 val = make_float4(0, 0, 0, 0);
        if (valid) {
            float4 y = ((const float4*)g_bufB)[v * 32 + q];
            float4 sc = ((const float4*)g_scale)[q];
            float4 sh = ((const float4*)g_shift)[q];
            val.x = fmaxf(fmaf(y.x, sc.x, sh.x), 0.0f);
            val.y = fmaxf(fmaf(y.y, sc.y, sh.y), 0.0f);
            val.z = fmaxf(fmaf(y.z, sc.z, sh.z), 0.0f);
            val.w = fmaxf(fmaf(y.w, sc.w, sh.w), 0.0f);
        }
        if (uni) {
#pragma unroll
            for (int o = 16; o; o >>= 1) {
                val.x += __shfl_xor_sync(0xffffffffu, val.x, o);
                val.y += __shfl_xor_sync(0xffffffffu, val.y, o);
                val.z += __shfl_xor_sync(0xffffffffu, val.z, o);
                val.w += __shfl_xor_sync(0xffffffffu, val.w, o);
            }
            if (lane == 0) {
                float* p = &g_hg[g0 * DD + q * 4];
                atomicAdd(p + 0, val.x);
                atomicAdd(p + 1, val.y);
                atomicAdd(p + 2, val.z);
                atomicAdd(p + 3, val.w);
            }
        } else if (valid) {
            float* p = &g_hg[g * DD + q * 4];
            atomicAdd(p + 0, val.x);
            atomicAdd(p + 1, val.y);
            atomicAdd(p + 2, val.z);
            atomicAdd(p + 3, val.w);
        }
    }
}

// head: mean -> fc1 relu -> fc2   (one block per graph, 64 threads)
__global__ void k_head(const float* __restrict__ fcW1, const float* __restrict__ fcb1,
                       const float* __restrict__ fcW2, const float* __restrict__ fcb2,
                       float* __restrict__ out) {
    int g = blockIdx.x, t = threadIdx.x;      // 64 threads
    __shared__ float hg[DD];
    __shared__ float s0[64], s1[64];
    float inv = 1.0f / (float)max(g_gcnt[g], 1);
    for (int k = t; k < DD; k += 64) hg[k] = g_hg[g * DD + k] * inv;
    __syncthreads();
    float z = fcb1[t];
#pragma unroll
    for (int k = 0; k < DD; k++) z = fmaf(hg[k], fcW1[k * 64 + t], z);
    z = fmaxf(z, 0.0f);
    s0[t] = z * fcW2[t * 2 + 0];
    s1[t] = z * fcW2[t * 2 + 1];
    __syncthreads();
    if (t == 0) {
        float a = 0.0f, b = 0.0f;
        for (int j = 0; j < 64; j++) { a += s0[j]; b += s1[j]; }
        out[g * 2 + 0] = a + fcb2[0];
        out[g * 2 + 1] = b + fcb2[1];
    }
}

// ---------------- launch ----------------
extern "C" void kernel_launch(void* const* d_in, const int* in_sizes, int n_in,
                              void* d_out, int out_size) {
    const int* tokens = (const int*)d_in[0];
    const int* src    = (const int*)d_in[1];
    const int* dst    = (const int*)d_in[2];
    const int* gids   = (const int*)d_in[3];
    const float* embed = (const float*)d_in[4];
    const float* W[3]  = {(const float*)d_in[5], (const float*)d_in[9],  (const float*)d_in[13]};
    const float* bW[3] = {(const float*)d_in[6], (const float*)d_in[10], (const float*)d_in[14]};
    const float* ga[3] = {(const float*)d_in[7], (const float*)d_in[11], (const float*)d_in[15]};
    const float* be[3] = {(const float*)d_in[8], (const float*)d_in[12], (const float*)d_in[16]};
    const float* fcW1 = (const float*)d_in[17];
    const float* fcb1 = (const float*)d_in[18];
    const float* fcW2 = (const float*)d_in[19];
    const float* fcb2 = (const float*)d_in[20];
    float* out = (float*)d_out;

    k_zero<<<391, 256>>>();
    k_deg<<<6250, 256>>>(src, dst);
    k_gcnt<<<391, 256>>>(gids);
    k_norm<<<391, 256>>>();
    k_scan1<<<NBS, 1024>>>();
    k_scan2<<<1, 32>>>();
    k_scan3<<<NBS, 1024>>>();
    k_scatter<<<6250, 256>>>(src, dst);
    k_embed<<<12500, 256>>>(tokens, embed);

    for (int l = 0; l < 3; l++) {
        k_agg<<<12500, 256>>>();
        k_gemm<<<1563, 128>>>(W[l], bW[l]);
        k_zstat<<<1, 128>>>();
        k_stat<<<512, 128>>>();
        k_bnfinal<<<1, 128>>>(ga[l], be[l]);
        if (l < 2)
            k_apply<<<12500, 256>>>();
        else
            k_pool<<<3125, 256>>>(gids);
    }
    k_head<<<64, 64>>>(fcW1, fcb1, fcW2, fcb2, out);
}

// round 2
// speedup vs baseline: 1.4777x; 1.4777x over previous
#include <cuda_runtime.h>
#include <cuda_bf16.h>

#define NN 100000
#define NE 1600000
#define NG 64
#define DD 128
#define NBS 98            // ceil(100000/1024)
#define EPSX 1e-5f

// ---------------- scratch (static device globals; no allocation) ----------------
__device__ __align__(16) uint2 g_bufA[NN * 32];   // bf16 message-ready features (128 bf16 = 32 uint2 / node)
__device__ __align__(16) float g_bufB[NN * DD];   // agg / gemm output (fp32, in-place)
__device__ int   g_csr[NE];
__device__ int   g_off[NN];
__device__ int   g_cur[NN];
__device__ int   g_degin[NN];
__device__ int   g_degout[NN];
__device__ float g_nsrc[NN];
__device__ float g_ndst[NN];
__device__ int   g_part[NBS];
__device__ int   g_partoff[NBS];
__device__ __align__(16) float g_sum[DD];
__device__ __align__(16) float g_sq[DD];
__device__ __align__(16) float g_scale[DD];
__device__ __align__(16) float g_shift[DD];
__device__ int   g_gcnt[NG];
__device__ __align__(16) float g_hg[NG * DD];

// ---------------- fp32x2 packed-FMA helpers (Blackwell sm_100+) ----------------
__device__ __forceinline__ unsigned long long pk2(float a) {
    unsigned long long r;
    asm("mov.b64 %0, {%1, %1};" : "=l"(r) : "f"(a));
    return r;
}
__device__ __forceinline__ unsigned long long fma2(unsigned long long a,
                                                   unsigned long long b,
                                                   unsigned long long c) {
    unsigned long long d;
    asm("fma.rn.f32x2 %0, %1, %2, %3;" : "=l"(d) : "l"(a), "l"(b), "l"(c));
    return d;
}
__device__ __forceinline__ float2 upk2(unsigned long long v) {
    float2 f;
    asm("mov.b64 {%0, %1}, %2;" : "=f"(f.x), "=f"(f.y) : "l"(v));
    return f;
}

// pack 4 floats -> uint2 of 4 bf16 (rn)
__device__ __forceinline__ uint2 pack_bf16x4(float a, float b, float c, float d) {
    __nv_bfloat162 lo = __floats2bfloat162_rn(a, b);
    __nv_bfloat162 hi = __floats2bfloat162_rn(c, d);
    uint2 u;
    u.x = *reinterpret_cast<unsigned int*>(&lo);
    u.y = *reinterpret_cast<unsigned int*>(&hi);
    return u;
}

// ---------------- setup kernels ----------------
__global__ void k_zero() {
    int i = blockIdx.x * 256 + threadIdx.x;
    if (i < NN) { g_degin[i] = 0; g_degout[i] = 0; }
    if (i < NG) g_gcnt[i] = 0;
    if (i < NG * DD) g_hg[i] = 0.0f;
    if (i < DD) { g_sum[i] = 0.0f; g_sq[i] = 0.0f; }
}

// edge degrees + (for e < NN) graph counts, warp-aggregated (graph_ids sorted)
__global__ void k_deg(const int* __restrict__ src, const int* __restrict__ dst,
                      const int* __restrict__ gids) {
    int e = blockIdx.x * 256 + threadIdx.x;
    if (e < NE) {
        atomicAdd(&g_degout[src[e]], 1);
        atomicAdd(&g_degin[dst[e]], 1);
    }
    bool valid = e < NN;
    int g = valid ? gids[e] : -1;
    int g0 = __shfl_sync(0xffffffffu, g, 0);
    if (__all_sync(0xffffffffu, g == g0)) {
        if ((threadIdx.x & 31) == 0 && g0 >= 0) atomicAdd(&g_gcnt[g0], 32);
    } else if (valid) {
        atomicAdd(&g_gcnt[g], 1);
    }
}

__global__ void k_scan1() {
    int tid = threadIdx.x;
    int gid = blockIdx.x * 1024 + tid;
    int v = (gid < NN) ? g_degin[gid] : 0;
    int lane = tid & 31, w = tid >> 5;
    int x = v;
#pragma unroll
    for (int o = 1; o < 32; o <<= 1) {
        int y = __shfl_up_sync(0xffffffffu, x, o);
        if (lane >= o) x += y;
    }
    __shared__ int ws[32];
    if (lane == 31) ws[w] = x;
    __syncthreads();
    if (w == 0) {
        int y = ws[lane];
#pragma unroll
        for (int o = 1; o < 32; o <<= 1) {
            int z = __shfl_up_sync(0xffffffffu, y, o);
            if (lane >= o) y += z;
        }
        ws[lane] = y;
    }
    __syncthreads();
    int incl = x + (w ? ws[w - 1] : 0);
    if (gid < NN) g_off[gid] = incl - v;    // exclusive
    if (tid == 1023) g_part[blockIdx.x] = incl;
}

__global__ void k_scan2() {
    if (threadIdx.x == 0) {
        int acc = 0;
        for (int i = 0; i < NBS; i++) { int t = g_part[i]; g_partoff[i] = acc; acc += t; }
    }
}

// finalize offsets + compute both degree norms
__global__ void k_scan3() {
    int gid = blockIdx.x * 1024 + threadIdx.x;
    if (gid < NN) {
        int o = g_off[gid] + g_partoff[blockIdx.x];
        g_off[gid] = o;
        g_cur[gid] = o;
        g_nsrc[gid] = rsqrtf((float)max(g_degout[gid], 1));
        g_ndst[gid] = rsqrtf((float)max(g_degin[gid], 1));
    }
}

__global__ void k_scatter(const int* __restrict__ src, const int* __restrict__ dst) {
    int e = blockIdx.x * 256 + threadIdx.x;
    if (e < NE) {
        int d = dst[e];
        int pos = atomicAdd(&g_cur[d], 1);
        g_csr[pos] = src[e];
    }
}

// h0 = bf16(embed[tokens] * norm_src)
__global__ void k_embed(const int* __restrict__ tokens, const float* __restrict__ embed) {
    int idx = blockIdx.x * 256 + threadIdx.x;
    if (idx >= NN * 32) return;
    int v = idx >> 5, q = idx & 31;
    int t = tokens[v];
    float4 e = ((const float4*)embed)[t * 32 + q];
    float ns = g_nsrc[v];
    g_bufA[idx] = pack_bf16x4(e.x * ns, e.y * ns, e.z * ns, e.w * ns);
}

// ---------------- per-layer kernels ----------------
// agg[v] = norm_dst[v] * sum_{e: dst=v} bufA[src[e]]   (one warp per node, bf16 msgs)
__global__ void k_agg() {
    int wid = blockIdx.x * 8 + (threadIdx.x >> 5);
    int lane = threadIdx.x & 31;
    if (wid >= NN) return;
    int off = g_off[wid];
    int deg = g_degin[wid];
    float2 a0 = make_float2(0, 0), a1 = make_float2(0, 0);
    float2 b0 = make_float2(0, 0), b1 = make_float2(0, 0);
    for (int base = 0; base < deg; base += 32) {
        int n = min(32, deg - base);
        int idx = (base + lane < deg) ? g_csr[off + base + lane] : 0;
        int j = 0;
        for (; j + 1 < n; j += 2) {
            int s0 = __shfl_sync(0xffffffffu, idx, j);
            int s1 = __shfl_sync(0xffffffffu, idx, j + 1);
            uint2 m0 = g_bufA[s0 * 32 + lane];
            uint2 m1 = g_bufA[s1 * 32 + lane];
            float2 f;
            f = __bfloat1622float2(*reinterpret_cast<__nv_bfloat162*>(&m0.x));
            a0.x += f.x; a0.y += f.y;
            f = __bfloat1622float2(*reinterpret_cast<__nv_bfloat162*>(&m0.y));
            a1.x += f.x; a1.y += f.y;
            f = __bfloat1622float2(*reinterpret_cast<__nv_bfloat162*>(&m1.x));
            b0.x += f.x; b0.y += f.y;
            f = __bfloat1622float2(*reinterpret_cast<__nv_bfloat162*>(&m1.y));
            b1.x += f.x; b1.y += f.y;
        }
        if (j < n) {
            int s0 = __shfl_sync(0xffffffffu, idx, j);
            uint2 m0 = g_bufA[s0 * 32 + lane];
            float2 f;
            f = __bfloat1622float2(*reinterpret_cast<__nv_bfloat162*>(&m0.x));
            a0.x += f.x; a0.y += f.y;
            f = __bfloat1622float2(*reinterpret_cast<__nv_bfloat162*>(&m0.y));
            a1.x += f.x; a1.y += f.y;
        }
    }
    float nd = g_ndst[wid];
    float4 r;
    r.x = (a0.x + b0.x) * nd;
    r.y = (a0.y + b0.y) * nd;
    r.z = (a1.x + b1.x) * nd;
    r.w = (a1.y + b1.y) * nd;
    ((float4*)g_bufB)[wid * 32 + lane] = r;
}

// in-place  bufB = bufB @ W + b, plus fused BN column statistics
__global__ __launch_bounds__(128) void k_gemm(const float* __restrict__ W,
                                              const float* __restrict__ bias) {
    __shared__ float Wsm[32 * 128];   // one 32-row K chunk of W
    __shared__ float Xs[32 * 68];     // transposed X chunk [k][r], pad 68
    __shared__ float sS[DD], sQ[DD];
    int tid = threadIdx.x;
    int tx = tid & 15, ty = tid >> 4;
    int rbase = blockIdx.x * 64;
    unsigned long long c2[8][4];
#pragma unroll
    for (int i = 0; i < 8; i++)
#pragma unroll
        for (int j = 0; j < 4; j++) c2[i][j] = 0ull;
    if (tid < DD) { sS[tid] = 0.0f; sQ[tid] = 0.0f; }

    const float4* io4 = (const float4*)g_bufB;

    for (int kc = 0; kc < 4; kc++) {
        const float4* Wg = (const float4*)(W + kc * 32 * 128);
        float4* Ws4 = (float4*)Wsm;
#pragma unroll
        for (int i = 0; i < 8; i++) Ws4[tid + i * 128] = Wg[tid + i * 128];
#pragma unroll
        for (int i = 0; i < 4; i++) {
            int f = tid + i * 128;
            int r = f >> 3;
            int k4 = f & 7;
            float4 v = make_float4(0, 0, 0, 0);
            int row = rbase + r;
            if (row < NN) v = io4[row * 32 + kc * 8 + k4];
            Xs[(k4 * 4 + 0) * 68 + r] = v.x;
            Xs[(k4 * 4 + 1) * 68 + r] = v.y;
            Xs[(k4 * 4 + 2) * 68 + r] = v.z;
            Xs[(k4 * 4 + 3) * 68 + r] = v.w;
        }
        __syncthreads();
#pragma unroll 8
        for (int k = 0; k < 32; k++) {
            float4 av0 = *(const float4*)&Xs[k * 68 + ty * 8];
            float4 av1 = *(const float4*)&Xs[k * 68 + ty * 8 + 4];
            const unsigned long long* wrow =
                (const unsigned long long*)&Wsm[k * 128 + tx * 8];
            unsigned long long w0 = wrow[0], w1 = wrow[1], w2 = wrow[2], w3 = wrow[3];
            float a[8] = {av0.x, av0.y, av0.z, av0.w, av1.x, av1.y, av1.z, av1.w};
#pragma unroll
            for (int i = 0; i < 8; i++) {
                unsigned long long ap = pk2(a[i]);
                c2[i][0] = fma2(ap, w0, c2[i][0]);
                c2[i][1] = fma2(ap, w1, c2[i][1]);
                c2[i][2] = fma2(ap, w2, c2[i][2]);
                c2[i][3] = fma2(ap, w3, c2[i][3]);
            }
        }
        __syncthreads();
    }
    // epilogue: bias + store + per-column stats
    float4 bi0 = *(const float4*)&bias[tx * 8];
    float4 bi1 = *(const float4*)&bias[tx * 8 + 4];
    float4* out4 = (float4*)g_bufB;
    float cs[8] = {0, 0, 0, 0, 0, 0, 0, 0};
    float cq[8] = {0, 0, 0, 0, 0, 0, 0, 0};
#pragma unroll
    for (int i = 0; i < 8; i++) {
        int row = rbase + ty * 8 + i;
        if (row >= NN) break;
        float2 p0 = upk2(c2[i][0]), p1 = upk2(c2[i][1]);
        float2 p2 = upk2(c2[i][2]), p3 = upk2(c2[i][3]);
        float o[8];
        o[0] = p0.x + bi0.x; o[1] = p0.y + bi0.y; o[2] = p1.x + bi0.z; o[3] = p1.y + bi0.w;
        o[4] = p2.x + bi1.x; o[5] = p2.y + bi1.y; o[6] = p3.x + bi1.z; o[7] = p3.y + bi1.w;
#pragma unroll
        for (int j = 0; j < 8; j++) { cs[j] += o[j]; cq[j] += o[j] * o[j]; }
        out4[row * 32 + tx * 2]     = make_float4(o[0], o[1], o[2], o[3]);
        out4[row * 32 + tx * 2 + 1] = make_float4(o[4], o[5], o[6], o[7]);
    }
    __syncthreads();  // sS/sQ init visible
#pragma unroll
    for (int j = 0; j < 8; j++) {
        atomicAdd(&sS[tx * 8 + j], cs[j]);
        atomicAdd(&sQ[tx * 8 + j], cq[j]);
    }
    __syncthreads();
    if (tid < DD) {
        atomicAdd(&g_sum[tid], sS[tid]);
        atomicAdd(&g_sq[tid], sQ[tid]);
    }
}

// finalize BN affine, then re-zero stat accumulators for the next layer
__global__ void k_bnfinal(const float* __restrict__ gamma, const float* __restrict__ beta) {
    int c = threadIdx.x;
    const float invn = 1.0f / (float)NN;
    float mu = g_sum[c] * invn;
    float var = g_sq[c] * invn - mu * mu;
    var = fmaxf(var, 0.0f);
    float sc = gamma[c] * rsqrtf(var + EPSX);
    g_scale[c] = sc;
    g_shift[c] = beta[c] - mu * sc;
    g_sum[c] = 0.0f;
    g_sq[c] = 0.0f;
}

// layers 0/1: bufA = bf16(relu(bn(bufB)) * norm_src)
__global__ void k_apply() {
    int idx = blockIdx.x * 256 + threadIdx.x;
    if (idx >= NN * 32) return;
    int v = idx >> 5, q = idx & 31;
    float4 y = ((const float4*)g_bufB)[idx];
    float4 sc = ((const float4*)g_scale)[q];
    float4 sh = ((const float4*)g_shift)[q];
    float ns = g_nsrc[v];
    float rx = fmaxf(fmaf(y.x, sc.x, sh.x), 0.0f) * ns;
    float ry = fmaxf(fmaf(y.y, sc.y, sh.y), 0.0f) * ns;
    float rz = fmaxf(fmaf(y.z, sc.z, sh.z), 0.0f) * ns;
    float rw = fmaxf(fmaf(y.w, sc.w, sh.w), 0.0f) * ns;
    g_bufA[idx] = pack_bf16x4(rx, ry, rz, rw);
}

// layer 2: relu(bn(bufB)) pooled per graph (warp-reduced; graph_ids sorted)
__global__ void k_pool(const int* __restrict__ gids) {
    int w = threadIdx.x >> 5, lane = threadIdx.x & 31;
    int v = blockIdx.x * 32 + lane;
    bool valid = v < NN;
    int g = valid ? gids[v] : 0;
    int g0 = __shfl_sync(0xffffffffu, g, 0);
    bool uni = __all_sync(0xffffffffu, valid && g == g0);
#pragma unroll
    for (int qq = 0; qq < 4; qq++) {
        int q = w * 4 + qq;
        float4 val = make_float4(0, 0, 0, 0);
        if (valid) {
            float4 y = ((const float4*)g_bufB)[v * 32 + q];
            float4 sc = ((const float4*)g_scale)[q];
            float4 sh = ((const float4*)g_shift)[q];
            val.x = fmaxf(fmaf(y.x, sc.x, sh.x), 0.0f);
            val.y = fmaxf(fmaf(y.y, sc.y, sh.y), 0.0f);
            val.z = fmaxf(fmaf(y.z, sc.z, sh.z), 0.0f);
            val.w = fmaxf(fmaf(y.w, sc.w, sh.w), 0.0f);
        }
        if (uni) {
#pragma unroll
            for (int o = 16; o; o >>= 1) {
                val.x += __shfl_xor_sync(0xffffffffu, val.x, o);
                val.y += __shfl_xor_sync(0xffffffffu, val.y, o);
                val.z += __shfl_xor_sync(0xffffffffu, val.z, o);
                val.w += __shfl_xor_sync(0xffffffffu, val.w, o);
            }
            if (lane == 0) {
                float* p = &g_hg[g0 * DD + q * 4];
                atomicAdd(p + 0, val.x);
                atomicAdd(p + 1, val.y);
                atomicAdd(p + 2, val.z);
                atomicAdd(p + 3, val.w);
            }
        } else if (valid) {
            float* p = &g_hg[g * DD + q * 4];
            atomicAdd(p + 0, val.x);
            atomicAdd(p + 1, val.y);
            atomicAdd(p + 2, val.z);
            atomicAdd(p + 3, val.w);
        }
    }
}

// head: mean -> fc1 relu -> fc2   (one block per graph, 64 threads)
__global__ void k_head(const float* __restrict__ fcW1, const float* __restrict__ fcb1,
                       const float* __restrict__ fcW2, const float* __restrict__ fcb2,
                       float* __restrict__ out) {
    int g = blockIdx.x, t = threadIdx.x;
    __shared__ float hg[DD];
    __shared__ float s0[64], s1[64];
    float inv = 1.0f / (float)max(g_gcnt[g], 1);
    for (int k = t; k < DD; k += 64) hg[k] = g_hg[g * DD + k] * inv;
    __syncthreads();
    float z = fcb1[t];
#pragma unroll
    for (int k = 0; k < DD; k++) z = fmaf(hg[k], fcW1[k * 64 + t], z);
    z = fmaxf(z, 0.0f);
    s0[t] = z * fcW2[t * 2 + 0];
    s1[t] = z * fcW2[t * 2 + 1];
    __syncthreads();
    if (t == 0) {
        float a = 0.0f, b = 0.0f;
        for (int j = 0; j < 64; j++) { a += s0[j]; b += s1[j]; }
        out[g * 2 + 0] = a + fcb2[0];
        out[g * 2 + 1] = b + fcb2[1];
    }
}

// ---------------- launch ----------------
extern "C" void kernel_launch(void* const* d_in, const int* in_sizes, int n_in,
                              void* d_out, int out_size) {
    const int* tokens = (const int*)d_in[0];
    const int* src    = (const int*)d_in[1];
    const int* dst    = (const int*)d_in[2];
    const int* gids   = (const int*)d_in[3];
    const float* embed = (const float*)d_in[4];
    const float* W[3]  = {(const float*)d_in[5], (const float*)d_in[9],  (const float*)d_in[13]};
    const float* bW[3] = {(const float*)d_in[6], (const float*)d_in[10], (const float*)d_in[14]};
    const float* ga[3] = {(const float*)d_in[7], (const float*)d_in[11], (const float*)d_in[15]};
    const float* be[3] = {(const float*)d_in[8], (const float*)d_in[12], (const float*)d_in[16]};
    const float* fcW1 = (const float*)d_in[17];
    const float* fcb1 = (const float*)d_in[18];
    const float* fcW2 = (const float*)d_in[19];
    const float* fcb2 = (const float*)d_in[20];
    float* out = (float*)d_out;

    k_zero<<<391, 256>>>();
    k_deg<<<6250, 256>>>(src, dst, gids);
    k_scan1<<<NBS, 1024>>>();
    k_scan2<<<1, 32>>>();
    k_scan3<<<NBS, 1024>>>();
    k_scatter<<<6250, 256>>>(src, dst);
    k_embed<<<12500, 256>>>(tokens, embed);

    for (int l = 0; l < 3; l++) {
        k_agg<<<12500, 256>>>();
        k_gemm<<<1563, 128>>>(W[l], bW[l]);
        k_bnfinal<<<1, 128>>>(ga[l], be[l]);
        if (l < 2)
            k_apply<<<12500, 256>>>();
        else
            k_pool<<<3125, 256>>>(gids);
    }
    k_head<<<64, 64>>>(fcW1, fcb1, fcW2, fcb2, out);
}

// round 7
// speedup vs baseline: 1.8707x; 1.2660x over previous
#include <cuda_runtime.h>
#include <cuda_bf16.h>
#include <cstdint>

#define NN 100000
#define NE 1600000
#define NG 64
#define DD 128
#define NBS 98            // ceil(100000/1024)
#define NTILE 782         // ceil(100000/128)
#define EPSX 1e-5f

// ---------------- scratch (static device globals; no allocation) ----------------
__device__ __align__(16) uint2 g_bufA[NN * 32];         // bf16 messages (row-major, 256B/node)
__device__ __align__(16) float g_bufB[NN * DD];         // gemm output fp32
__device__ __align__(16) uint2 g_bufX[NTILE * 128 * 32];// bf16 agg output rows (pad rows zeroed)
__device__ __align__(16) char  g_Wbf[3 * 32768];        // bf16 weights, [n][k] layout per layer
__device__ int   g_csr[NE];
__device__ int   g_off[NN];
__device__ int   g_cur[NN];
__device__ int   g_degin[NN];
__device__ int   g_degout[NN];
__device__ float g_nsrc[NN];
__device__ float g_ndst[NN];
__device__ int   g_part[NBS];
__device__ int   g_partoff[NBS];
__device__ __align__(16) float g_sum[DD];
__device__ __align__(16) float g_sq[DD];
__device__ __align__(16) float g_scale[DD];
__device__ __align__(16) float g_shift[DD];
__device__ int   g_gcnt[NG];
__device__ __align__(16) float g_hg[NG * DD];

// ---------------- helpers ----------------
__device__ __forceinline__ uint2 pack_bf16x4(float a, float b, float c, float d) {
    __nv_bfloat162 lo = __floats2bfloat162_rn(a, b);
    __nv_bfloat162 hi = __floats2bfloat162_rn(c, d);
    uint2 u;
    u.x = *reinterpret_cast<unsigned int*>(&lo);
    u.y = *reinterpret_cast<unsigned int*>(&hi);
    return u;
}

__device__ __forceinline__ uint32_t smem_u32(const void* p) {
    uint32_t a;
    asm("{ .reg .u64 t; cvta.to.shared.u64 t, %1; cvt.u32.u64 %0, t; }" : "=r"(a) : "l"(p));
    return a;
}

// ---------------- setup kernels ----------------
__global__ void k_zero() {
    int i = blockIdx.x * 256 + threadIdx.x;
    if (i < NN) { g_degin[i] = 0; g_degout[i] = 0; }
    if (i < NG) g_gcnt[i] = 0;
    if (i < NG * DD) g_hg[i] = 0.0f;
    if (i < DD) { g_sum[i] = 0.0f; g_sq[i] = 0.0f; }
    if (i < (NTILE * 128 - NN) * 32) g_bufX[NN * 32 + i] = make_uint2(0, 0);  // pad rows
}

__global__ void k_deg(const int* __restrict__ src, const int* __restrict__ dst,
                      const int* __restrict__ gids) {
    int e = blockIdx.x * 256 + threadIdx.x;
    if (e < NE) {
        atomicAdd(&g_degout[src[e]], 1);
        atomicAdd(&g_degin[dst[e]], 1);
    }
    bool valid = e < NN;
    int g = valid ? gids[e] : -1;
    int g0 = __shfl_sync(0xffffffffu, g, 0);
    if (__all_sync(0xffffffffu, g == g0)) {
        if ((threadIdx.x & 31) == 0 && g0 >= 0) atomicAdd(&g_gcnt[g0], 32);
    } else if (valid) {
        atomicAdd(&g_gcnt[g], 1);
    }
}

__global__ void k_scan1() {
    int tid = threadIdx.x;
    int gid = blockIdx.x * 1024 + tid;
    int v = (gid < NN) ? g_degin[gid] : 0;
    int lane = tid & 31, w = tid >> 5;
    int x = v;
#pragma unroll
    for (int o = 1; o < 32; o <<= 1) {
        int y = __shfl_up_sync(0xffffffffu, x, o);
        if (lane >= o) x += y;
    }
    __shared__ int ws[32];
    if (lane == 31) ws[w] = x;
    __syncthreads();
    if (w == 0) {
        int y = ws[lane];
#pragma unroll
        for (int o = 1; o < 32; o <<= 1) {
            int z = __shfl_up_sync(0xffffffffu, y, o);
            if (lane >= o) y += z;
        }
        ws[lane] = y;
    }
    __syncthreads();
    int incl = x + (w ? ws[w - 1] : 0);
    if (gid < NN) g_off[gid] = incl - v;
    if (tid == 1023) g_part[blockIdx.x] = incl;
}

// parallel scan of 98 block partials (1 block, 128 threads)
__global__ void k_scan2() {
    int tid = threadIdx.x;
    int lane = tid & 31, w = tid >> 5;
    int v = (tid < NBS) ? g_part[tid] : 0;
    int x = v;
#pragma unroll
    for (int o = 1; o < 32; o <<= 1) {
        int y = __shfl_up_sync(0xffffffffu, x, o);
        if (lane >= o) x += y;
    }
    __shared__ int ws[4];
    if (lane == 31) ws[w] = x;
    __syncthreads();
    int add = 0;
#pragma unroll
    for (int i = 0; i < 4; i++) if (i < w) add += ws[i];
    if (tid < NBS) g_partoff[tid] = x - v + add;
}

__global__ void k_scan3() {
    int gid = blockIdx.x * 1024 + threadIdx.x;
    if (gid < NN) {
        int o = g_off[gid] + g_partoff[blockIdx.x];
        g_off[gid] = o;
        g_cur[gid] = o;
        g_nsrc[gid] = rsqrtf((float)max(g_degout[gid], 1));
        g_ndst[gid] = rsqrtf((float)max(g_degin[gid], 1));
    }
}

__global__ void k_scatter(const int* __restrict__ src, const int* __restrict__ dst) {
    int e = blockIdx.x * 256 + threadIdx.x;
    if (e < NE) {
        int d = dst[e];
        int pos = atomicAdd(&g_cur[d], 1);
        g_csr[pos] = src[e];
    }
}

// W[k][n] fp32 -> bf16 [n][k] (B col-major for mma.sync)
__global__ void k_wconv(const float* __restrict__ W0, const float* __restrict__ W1,
                        const float* __restrict__ W2) {
    int idx = blockIdx.x * 256 + threadIdx.x;
    if (idx >= 3 * 16384) return;
    int l = idx >> 14, rem = idx & 16383;
    int k = rem >> 7, n = rem & 127;
    const float* W = (l == 0) ? W0 : ((l == 1) ? W1 : W2);
    ((__nv_bfloat16*)(g_Wbf + l * 32768))[n * 128 + k] = __float2bfloat16(W[k * 128 + n]);
}

// h0 = bf16(embed[tokens] * norm_src)
__global__ void k_embed(const int* __restrict__ tokens, const float* __restrict__ embed) {
    int idx = blockIdx.x * 256 + threadIdx.x;
    if (idx >= NN * 32) return;
    int v = idx >> 5, q = idx & 31;
    int t = tokens[v];
    float4 e = ((const float4*)embed)[t * 32 + q];
    float ns = g_nsrc[v];
    g_bufA[idx] = pack_bf16x4(e.x * ns, e.y * ns, e.z * ns, e.w * ns);
}

// ---------------- per-layer kernels ----------------
// agg[v] = norm_dst[v] * sum bufA[src]; bf16 output row-major into g_bufX
__global__ void k_agg() {
    int nid = blockIdx.x * 8 + (threadIdx.x >> 5);
    int lane = threadIdx.x & 31;
    if (nid >= NN) return;
    int off = g_off[nid];
    int deg = g_degin[nid];
    float2 a0 = make_float2(0, 0), a1 = make_float2(0, 0);
    float2 b0 = make_float2(0, 0), b1 = make_float2(0, 0);
    for (int base = 0; base < deg; base += 32) {
        int n = min(32, deg - base);
        int idx = (base + lane < deg) ? g_csr[off + base + lane] : 0;
        int j = 0;
        for (; j + 1 < n; j += 2) {
            int s0 = __shfl_sync(0xffffffffu, idx, j);
            int s1 = __shfl_sync(0xffffffffu, idx, j + 1);
            uint2 m0 = g_bufA[s0 * 32 + lane];
            uint2 m1 = g_bufA[s1 * 32 + lane];
            float2 f;
            f = __bfloat1622float2(*reinterpret_cast<__nv_bfloat162*>(&m0.x));
            a0.x += f.x; a0.y += f.y;
            f = __bfloat1622float2(*reinterpret_cast<__nv_bfloat162*>(&m0.y));
            a1.x += f.x; a1.y += f.y;
            f = __bfloat1622float2(*reinterpret_cast<__nv_bfloat162*>(&m1.x));
            b0.x += f.x; b0.y += f.y;
            f = __bfloat1622float2(*reinterpret_cast<__nv_bfloat162*>(&m1.y));
            b1.x += f.x; b1.y += f.y;
        }
        if (j < n) {
            int s0 = __shfl_sync(0xffffffffu, idx, j);
            uint2 m0 = g_bufA[s0 * 32 + lane];
            float2 f;
            f = __bfloat1622float2(*reinterpret_cast<__nv_bfloat162*>(&m0.x));
            a0.x += f.x; a0.y += f.y;
            f = __bfloat1622float2(*reinterpret_cast<__nv_bfloat162*>(&m0.y));
            a1.x += f.x; a1.y += f.y;
        }
    }
    float nd = g_ndst[nid];
    g_bufX[nid * 32 + lane] = pack_bf16x4((a0.x + b0.x) * nd, (a0.y + b0.y) * nd,
                                          (a1.x + b1.x) * nd, (a1.y + b1.y) * nd);
}

// ---------------- mma.sync GEMM: bufB = X @ W + b, fused BN stats ----------------
// 256 threads = 8 warps; block tile 128 rows x 128 cols; K in 2 halves of 64.
// Warp w: rows [w*16, w*16+16), all 128 cols (16 n-tiles of m16n8k16).
#define XST 144   // padded smem row stride bytes (128B data + 16) -> conflict-free ldmatrix

__global__ __launch_bounds__(256) void k_gemm_mma(int layer, const float* __restrict__ bias) {
    __shared__ __align__(16) char Xs[128 * XST];
    __shared__ __align__(16) char Wt[128 * XST];
    __shared__ float sS[DD], sQ[DD], sB[DD];
    int tid = threadIdx.x, lane = tid & 31, w = tid >> 5;
    int base = blockIdx.x * 128;
    if (tid < DD) { sS[tid] = 0.0f; sQ[tid] = 0.0f; sB[tid] = bias[tid]; }

    float d[16][4];
#pragma unroll
    for (int t = 0; t < 16; t++)
#pragma unroll
        for (int j = 0; j < 4; j++) d[t][j] = 0.0f;

    const uint4* Xg = (const uint4*)g_bufX + (size_t)base * 16;   // 16 uint4 per row
    const uint4* Wg = (const uint4*)(g_Wbf + layer * 32768);

    int wrow = w * 16;
    uint32_t a_base = smem_u32(Xs + (wrow + (lane & 15)) * XST + (lane >> 4) * 16);
    uint32_t b_base = smem_u32(Wt + (lane & 7) * XST + ((lane >> 3) & 1) * 16);

#pragma unroll
    for (int kh = 0; kh < 2; kh++) {
        // stage 64-k half of X and W: 1024 uint4 each, 256 threads x 4
#pragma unroll
        for (int i = 0; i < 4; i++) {
            int f = tid + i * 256;
            int r = f >> 3, j = f & 7;
            *(uint4*)(Xs + r * XST + j * 16) = Xg[r * 16 + kh * 8 + j];
            *(uint4*)(Wt + r * XST + j * 16) = Wg[r * 16 + kh * 8 + j];
        }
        __syncthreads();
#pragma unroll
        for (int ks = 0; ks < 4; ks++) {
            uint32_t a0, a1, a2, a3;
            asm volatile("ldmatrix.sync.aligned.m8n8.x4.shared.b16 {%0,%1,%2,%3}, [%4];"
                         : "=r"(a0), "=r"(a1), "=r"(a2), "=r"(a3)
                         : "r"(a_base + ks * 32));
#pragma unroll
            for (int t = 0; t < 16; t++) {
                uint32_t b0, b1;
                asm volatile("ldmatrix.sync.aligned.m8n8.x2.shared.b16 {%0,%1}, [%2];"
                             : "=r"(b0), "=r"(b1)
                             : "r"(b_base + t * 8 * XST + ks * 32));
                asm volatile(
                    "mma.sync.aligned.m16n8k16.row.col.f32.bf16.bf16.f32 "
                    "{%0,%1,%2,%3}, {%4,%5,%6,%7}, {%8,%9}, {%0,%1,%2,%3};"
                    : "+f"(d[t][0]), "+f"(d[t][1]), "+f"(d[t][2]), "+f"(d[t][3])
                    : "r"(a0), "r"(a1), "r"(a2), "r"(a3), "r"(b0), "r"(b1));
            }
        }
        __syncthreads();
    }

    // epilogue: bias + store + per-column stats
    int r0 = base + wrow + (lane >> 2);
    int r1 = r0 + 8;
    bool v0 = r0 < NN, v1 = r1 < NN;
#pragma unroll
    for (int t = 0; t < 16; t++) {
        int c0 = t * 8 + (lane & 3) * 2;
        float bb0 = sB[c0], bb1 = sB[c0 + 1];
        float d0 = v0 ? d[t][0] + bb0 : 0.0f;
        float d1 = v0 ? d[t][1] + bb1 : 0.0f;
        float d2 = v1 ? d[t][2] + bb0 : 0.0f;
        float d3 = v1 ? d[t][3] + bb1 : 0.0f;
        if (v0) *(float2*)&g_bufB[(size_t)r0 * DD + c0] = make_float2(d0, d1);
        if (v1) *(float2*)&g_bufB[(size_t)r1 * DD + c0] = make_float2(d2, d3);
        float s0 = d0 + d2, s1 = d1 + d3;
        float q0 = d0 * d0 + d2 * d2, q1 = d1 * d1 + d3 * d3;
#pragma unroll
        for (int o = 4; o < 32; o <<= 1) {
            s0 += __shfl_xor_sync(0xffffffffu, s0, o);
            s1 += __shfl_xor_sync(0xffffffffu, s1, o);
            q0 += __shfl_xor_sync(0xffffffffu, q0, o);
            q1 += __shfl_xor_sync(0xffffffffu, q1, o);
        }
        if (lane < 4) {
            atomicAdd(&sS[c0], s0);
            atomicAdd(&sS[c0 + 1], s1);
            atomicAdd(&sQ[c0], q0);
            atomicAdd(&sQ[c0 + 1], q1);
        }
    }
    __syncthreads();
    if (tid < DD) {
        atomicAdd(&g_sum[tid], sS[tid]);
        atomicAdd(&g_sq[tid], sQ[tid]);
    }
}

// finalize BN affine, then re-zero stat accumulators for the next layer
__global__ void k_bnfinal(const float* __restrict__ gamma, const float* __restrict__ beta) {
    int c = threadIdx.x;
    const float invn = 1.0f / (float)NN;
    float mu = g_sum[c] * invn;
    float var = g_sq[c] * invn - mu * mu;
    var = fmaxf(var, 0.0f);
    float sc = gamma[c] * rsqrtf(var + EPSX);
    g_scale[c] = sc;
    g_shift[c] = beta[c] - mu * sc;
    g_sum[c] = 0.0f;
    g_sq[c] = 0.0f;
}

// layers 0/1: bufA = bf16(relu(bn(bufB)) * norm_src)
__global__ void k_apply() {
    int idx = blockIdx.x * 256 + threadIdx.x;
    if (idx >= NN * 32) return;
    int v = idx >> 5, q = idx & 31;
    float4 y = ((const float4*)g_bufB)[idx];
    float4 sc = ((const float4*)g_scale)[q];
    float4 sh = ((const float4*)g_shift)[q];
    float ns = g_nsrc[v];
    float rx = fmaxf(fmaf(y.x, sc.x, sh.x), 0.0f) * ns;
    float ry = fmaxf(fmaf(y.y, sc.y, sh.y), 0.0f) * ns;
    float rz = fmaxf(fmaf(y.z, sc.z, sh.z), 0.0f) * ns;
    float rw = fmaxf(fmaf(y.w, sc.w, sh.w), 0.0f) * ns;
    g_bufA[idx] = pack_bf16x4(rx, ry, rz, rw);
}

// layer 2: relu(bn(bufB)) pooled per graph (warp-reduced; graph_ids sorted)
__global__ void k_pool(const int* __restrict__ gids) {
    int w = threadIdx.x >> 5, lane = threadIdx.x & 31;
    int v = blockIdx.x * 32 + lane;
    bool valid = v < NN;
    int g = valid ? gids[v] : 0;
    int g0 = __shfl_sync(0xffffffffu, g, 0);
    bool uni = __all_sync(0xffffffffu, valid && g == g0);
#pragma unroll
    for (int qq = 0; qq < 4; qq++) {
        int q = w * 4 + qq;
        float4 val = make_float4(0, 0, 0, 0);
        if (valid) {
            float4 y = ((const float4*)g_bufB)[v * 32 + q];
            float4 sc = ((const float4*)g_scale)[q];
            float4 sh = ((const float4*)g_shift)[q];
            val.x = fmaxf(fmaf(y.x, sc.x, sh.x), 0.0f);
            val.y = fmaxf(fmaf(y.y, sc.y, sh.y), 0.0f);
            val.z = fmaxf(fmaf(y.z, sc.z, sh.z), 0.0f);
            val.w = fmaxf(fmaf(y.w, sc.w, sh.w), 0.0f);
        }
        if (uni) {
#pragma unroll
            for (int o = 16; o; o >>= 1) {
                val.x += __shfl_xor_sync(0xffffffffu, val.x, o);
                val.y += __shfl_xor_sync(0xffffffffu, val.y, o);
                val.z += __shfl_xor_sync(0xffffffffu, val.z, o);
                val.w += __shfl_xor_sync(0xffffffffu, val.w, o);
            }
            if (lane == 0) {
                float* p = &g_hg[g0 * DD + q * 4];
                atomicAdd(p + 0, val.x);
                atomicAdd(p + 1, val.y);
                atomicAdd(p + 2, val.z);
                atomicAdd(p + 3, val.w);
            }
        } else if (valid) {
            float* p = &g_hg[g * DD + q * 4];
            atomicAdd(p + 0, val.x);
            atomicAdd(p + 1, val.y);
            atomicAdd(p + 2, val.z);
            atomicAdd(p + 3, val.w);
        }
    }
}

// head: mean -> fc1 relu -> fc2   (one block per graph, 64 threads)
__global__ void k_head(const float* __restrict__ fcW1, const float* __restrict__ fcb1,
                       const float* __restrict__ fcW2, const float* __restrict__ fcb2,
                       float* __restrict__ out) {
    int g = blockIdx.x, t = threadIdx.x;
    __shared__ float hg[DD];
    __shared__ float s0[64], s1[64];
    float inv = 1.0f / (float)max(g_gcnt[g], 1);
    for (int k = t; k < DD; k += 64) hg[k] = g_hg[g * DD + k] * inv;
    __syncthreads();
    float z = fcb1[t];
#pragma unroll
    for (int k = 0; k < DD; k++) z = fmaf(hg[k], fcW1[k * 64 + t], z);
    z = fmaxf(z, 0.0f);
    s0[t] = z * fcW2[t * 2 + 0];
    s1[t] = z * fcW2[t * 2 + 1];
    __syncthreads();
    if (t == 0) {
        float a = 0.0f, b = 0.0f;
        for (int j = 0; j < 64; j++) { a += s0[j]; b += s1[j]; }
        out[g * 2 + 0] = a + fcb2[0];
        out[g * 2 + 1] = b + fcb2[1];
    }
}

// ---------------- launch ----------------
extern "C" void kernel_launch(void* const* d_in, const int* in_sizes, int n_in,
                              void* d_out, int out_size) {
    const int* tokens = (const int*)d_in[0];
    const int* src    = (const int*)d_in[1];
    const int* dst    = (const int*)d_in[2];
    const int* gids   = (const int*)d_in[3];
    const float* embed = (const float*)d_in[4];
    const float* W[3]  = {(const float*)d_in[5], (const float*)d_in[9],  (const float*)d_in[13]};
    const float* bW[3] = {(const float*)d_in[6], (const float*)d_in[10], (const float*)d_in[14]};
    const float* ga[3] = {(const float*)d_in[7], (const float*)d_in[11], (const float*)d_in[15]};
    const float* be[3] = {(const float*)d_in[8], (const float*)d_in[12], (const float*)d_in[16]};
    const float* fcW1 = (const float*)d_in[17];
    const float* fcb1 = (const float*)d_in[18];
    const float* fcW2 = (const float*)d_in[19];
    const float* fcb2 = (const float*)d_in[20];
    float* out = (float*)d_out;

    k_zero<<<391, 256>>>();
    k_deg<<<6250, 256>>>(src, dst, gids);
    k_scan1<<<NBS, 1024>>>();
    k_scan2<<<1, 128>>>();
    k_scan3<<<NBS, 1024>>>();
    k_scatter<<<6250, 256>>>(src, dst);
    k_wconv<<<192, 256>>>(W[0], W[1], W[2]);
    k_embed<<<12500, 256>>>(tokens, embed);

    for (int l = 0; l < 3; l++) {
        k_agg<<<12500, 256>>>();
        k_gemm_mma<<<NTILE, 256>>>(l, bW[l]);
        k_bnfinal<<<1, 128>>>(ga[l], be[l]);
        if (l < 2)
            k_apply<<<12500, 256>>>();
        else
            k_pool<<<3125, 256>>>(gids);
    }
    k_head<<<64, 64>>>(fcW1, fcb1, fcW2, fcb2, out);
}